// round 9
// baseline (speedup 1.0000x reference)
#include <cuda_runtime.h>
#include <cstdint>

#define N_NODES 50000
#define N_EDGES 800000
#define N_FEATS 64
#define NQUADS  (N_EDGES / 4)
#define N_TILES (N_EDGES / 128)          // 6250, exact
#define SCAN_BLOCKS ((N_NODES + 255) / 256)   // 196
#define SRC_BYTES (N_NODES * 4)          // 200000 B, multiple of 16
#define SMEM_TOTAL (16 + SRC_BYTES)

// Scratch (allocation-free)
__device__ int      g_degi[N_NODES];     // degree INCLUDING self-loop
__device__ int      g_excl[N_NODES];
__device__ int      g_cursor[N_NODES];
__device__ int      g_bsum[256];
__device__ float    g_a[N_NODES];
__device__ float    g_b[N_NODES];
__device__ float    g_c[N_NODES];
__device__ unsigned g_sorted[N_EDGES];   // (row<<16)|col, sorted by col

__device__ __forceinline__ uint32_t smem_u32(const void* p) {
    uint32_t a;
    asm("{ .reg .u64 t; cvta.to.shared.u64 t, %1; cvt.u32.u64 %0, t; }"
        : "=r"(a) : "l"(p));
    return a;
}

// ---------------------------------------------------------------------------
// Projection y0 = x[i,:].w (warp per node) + deg init (self-loop = 1).
// ---------------------------------------------------------------------------
__global__ void k_proj(const float* __restrict__ x,
                       const float* __restrict__ W) {
    int warp = (blockIdx.x * blockDim.x + threadIdx.x) >> 5;
    int lane = threadIdx.x & 31;
    if (warp >= N_NODES) return;
    const float* xr = x + (size_t)warp * N_FEATS;
    float s = xr[lane] * __ldg(W + lane) + xr[lane + 32] * __ldg(W + lane + 32);
    #pragma unroll
    for (int off = 16; off > 0; off >>= 1)
        s += __shfl_xor_sync(0xFFFFFFFFu, s, off);
    if (lane == 0) {
        g_a[warp]    = s;
        g_degi[warp] = 1;   // self-loop
    }
}

// ---------------------------------------------------------------------------
// Integer degree histogram at destination (4 edges/thread).
// ---------------------------------------------------------------------------
__global__ void __launch_bounds__(256)
k_deg(const int* __restrict__ col) {
    int t = blockIdx.x * blockDim.x + threadIdx.x;
    if (t >= NQUADS) return;
    int4 c = reinterpret_cast<const int4*>(col)[t];
    atomicAdd(&g_degi[c.x], 1);
    atomicAdd(&g_degi[c.y], 1);
    atomicAdd(&g_degi[c.z], 1);
    atomicAdd(&g_degi[c.w], 1);
}

// ---------------------------------------------------------------------------
// Exclusive scan over EDGE-ONLY degrees (degi - 1): cursor space is exactly
// [0, N_EDGES) — no self-loop slots (that was the R5 bug: scanning degi
// left 50K garbage gaps and overflowed g_sorted).
// ---------------------------------------------------------------------------
__global__ void k_scan1() {   // per-block scan + block sums
    __shared__ int sh[256];
    int i = blockIdx.x * 256 + threadIdx.x;
    int v = (i < N_NODES) ? (g_degi[i] - 1) : 0;   // edge-only degree
    sh[threadIdx.x] = v;
    __syncthreads();
    #pragma unroll
    for (int d = 1; d < 256; d <<= 1) {
        int t = (threadIdx.x >= d) ? sh[threadIdx.x - d] : 0;
        __syncthreads();
        if (threadIdx.x >= d) sh[threadIdx.x] += t;
        __syncthreads();
    }
    if (i < N_NODES) g_excl[i] = sh[threadIdx.x] - v;
    if (threadIdx.x == 255) g_bsum[blockIdx.x] = sh[255];
}

__global__ void k_scan2() {   // scan the 196 block sums (single block)
    __shared__ int sh[256];
    int v = (threadIdx.x < SCAN_BLOCKS) ? g_bsum[threadIdx.x] : 0;
    sh[threadIdx.x] = v;
    __syncthreads();
    #pragma unroll
    for (int d = 1; d < 256; d <<= 1) {
        int t = (threadIdx.x >= d) ? sh[threadIdx.x - d] : 0;
        __syncthreads();
        if (threadIdx.x >= d) sh[threadIdx.x] += t;
        __syncthreads();
    }
    if (threadIdx.x < SCAN_BLOCKS) g_bsum[threadIdx.x] = sh[threadIdx.x] - v;
}

__global__ void k_scan3() {   // add block offsets -> scatter cursors
    int i = blockIdx.x * blockDim.x + threadIdx.x;
    if (i >= N_NODES) return;
    g_cursor[i] = g_excl[i] + g_bsum[i >> 8];
}

// ---------------------------------------------------------------------------
// Counting-sort scatter: edges grouped by destination (one-time cost,
// amortized across the 3 hop passes).
// ---------------------------------------------------------------------------
__global__ void __launch_bounds__(256)
k_scatter(const int* __restrict__ row, const int* __restrict__ col) {
    int t = blockIdx.x * blockDim.x + threadIdx.x;
    if (t >= NQUADS) return;
    int4 r = reinterpret_cast<const int4*>(row)[t];
    int4 c = reinterpret_cast<const int4*>(col)[t];
    int p0 = atomicAdd(&g_cursor[c.x], 1);
    int p1 = atomicAdd(&g_cursor[c.y], 1);
    int p2 = atomicAdd(&g_cursor[c.z], 1);
    int p3 = atomicAdd(&g_cursor[c.w], 1);
    g_sorted[p0] = ((unsigned)r.x << 16) | (unsigned)c.x;
    g_sorted[p1] = ((unsigned)r.y << 16) | (unsigned)c.y;
    g_sorted[p2] = ((unsigned)r.z << 16) | (unsigned)c.z;
    g_sorted[p3] = ((unsigned)r.w << 16) | (unsigned)c.w;
}

// ---------------------------------------------------------------------------
// u0 = rsqrt(deg)*y0 -> gather-source + accumulator (self-loop term).
// ---------------------------------------------------------------------------
__global__ void k_scale2() {
    int i = blockIdx.x * blockDim.x + threadIdx.x;
    if (i >= N_NODES) return;
    float v = rsqrtf((float)g_degi[i]) * g_a[i];
    g_b[i] = v;
    g_c[i] = v;
}

__global__ void k_div2(const float* __restrict__ s,
                       float* __restrict__ u, float* __restrict__ s2) {
    int i = blockIdx.x * blockDim.x + threadIdx.x;
    if (i >= N_NODES) return;
    float v = s[i] / (float)g_degi[i];
    u[i]  = v;
    s2[i] = v;
}

__global__ void k_final(float* __restrict__ out, const float* __restrict__ b) {
    int i = blockIdx.x * blockDim.x + threadIdx.x;
    if (i >= N_NODES) return;
    out[i] = rsqrtf((float)g_degi[i]) * out[i] + __ldg(b);
}

// ---------------------------------------------------------------------------
// Edge pass over DEST-SORTED edges: stage src (195KB) in SMEM via bulk-copy,
// then warp-contiguous processing — each RED instruction's 32 lanes hit ~2
// consecutive destination values (~1-2 sectors) instead of 32 random ones.
// ---------------------------------------------------------------------------
__global__ void __launch_bounds__(1024, 1)
k_edge_sorted(const float* __restrict__ src, float* __restrict__ dst) {
    extern __shared__ __align__(16) unsigned char smem_raw[];
    float* s_src = reinterpret_cast<float*>(smem_raw + 16);
    uint32_t mbar  = smem_u32(smem_raw);
    uint32_t sdata = mbar + 16;

    if (threadIdx.x == 0) {
        asm volatile("mbarrier.init.shared.b64 [%0], %1;"
                     :: "r"(mbar), "r"(1u) : "memory");
    }
    __syncthreads();
    if (threadIdx.x == 0) {
        asm volatile("mbarrier.arrive.expect_tx.shared.b64 _, [%0], %1;"
                     :: "r"(mbar), "r"((unsigned)SRC_BYTES) : "memory");
        #pragma unroll
        for (int c = 0; c < 4; c++) {
            asm volatile(
                "cp.async.bulk.shared::cta.global.mbarrier::complete_tx::bytes "
                "[%0], [%1], %2, [%3];"
                :: "r"(sdata + c * (SRC_BYTES / 4)),
                   "l"(src + (size_t)c * (N_NODES / 4)),
                   "r"((unsigned)(SRC_BYTES / 4)),
                   "r"(mbar)
                : "memory");
        }
    }
    {
        uint32_t done;
        asm volatile(
            "{\n\t.reg .pred p;\n\t"
            "mbarrier.try_wait.parity.acquire.cta.shared::cta.b64 p, [%1], %2;\n\t"
            "selp.b32 %0, 1, 0, p;\n\t}"
            : "=r"(done) : "r"(mbar), "r"(0u) : "memory");
        if (!done) {
            asm volatile(
                "{\n\t.reg .pred P1;\n\t"
                "WL_%=:\n\t"
                "mbarrier.try_wait.parity.acquire.cta.shared::cta.b64 P1, [%0], %1, 0x989680;\n\t"
                "@P1 bra.uni WD_%=;\n\t"
                "bra.uni WL_%=;\n\t"
                "WD_%=:\n\t}"
                :: "r"(mbar), "r"(0u) : "memory");
        }
    }

    // 128 sorted edges per warp-tile; lane l takes edges base+32k+l so each
    // RED instruction's lanes are consecutive in sorted (destination) order.
    int warp  = (blockIdx.x * blockDim.x + threadIdx.x) >> 5;
    int lane  = threadIdx.x & 31;
    int nwarp = (gridDim.x * blockDim.x) >> 5;
    for (int tile = warp; tile < N_TILES; tile += nwarp) {
        int base = tile * 128 + lane;
        unsigned p0 = g_sorted[base];
        unsigned p1 = g_sorted[base + 32];
        unsigned p2 = g_sorted[base + 64];
        unsigned p3 = g_sorted[base + 96];
        float v0 = s_src[p0 >> 16];
        float v1 = s_src[p1 >> 16];
        float v2 = s_src[p2 >> 16];
        float v3 = s_src[p3 >> 16];
        atomicAdd(dst + (p0 & 0xFFFFu), v0);
        atomicAdd(dst + (p1 & 0xFFFFu), v1);
        atomicAdd(dst + (p2 & 0xFFFFu), v2);
        atomicAdd(dst + (p3 & 0xFFFFu), v3);
    }
}

extern "C" void kernel_launch(void* const* d_in, const int* in_sizes, int n_in,
                              void* d_out, int out_size) {
    const float* x  = (const float*)d_in[0];
    const int*   ei = (const int*)d_in[1];   // [2, N_EDGES]
    const float* W  = (const float*)d_in[2]; // [1, N_FEATS]
    const float* b  = (const float*)d_in[3]; // [1]
    float* out = (float*)d_out;              // [N_NODES, 1]

    const int* row = ei;
    const int* col = ei + N_EDGES;

    float* ap; cudaGetSymbolAddress((void**)&ap, g_a);
    float* bp; cudaGetSymbolAddress((void**)&bp, g_b);
    float* cp; cudaGetSymbolAddress((void**)&cp, g_c);

    static bool attr_set = false;
    if (!attr_set) {
        cudaFuncSetAttribute(k_edge_sorted,
                             cudaFuncAttributeMaxDynamicSharedMemorySize,
                             SMEM_TOTAL);
        attr_set = true;
    }

    const int TB = 256;
    int grid_nodes = (N_NODES + TB - 1) / TB;
    int grid_proj  = (N_NODES * 32 + TB - 1) / TB;
    int grid_quads = (NQUADS + TB - 1) / TB;
    int grid_edge  = 152;   // one 195KB-smem block per SM

    // Preprocess: projection, degrees, scan, destination-sorted edge list.
    k_proj<<<grid_proj, TB>>>(x, W);
    k_deg<<<grid_quads, TB>>>(col);
    k_scan1<<<SCAN_BLOCKS, 256>>>();
    k_scan2<<<1, 256>>>();
    k_scan3<<<grid_nodes, TB>>>();
    k_scatter<<<grid_quads, TB>>>(row, col);

    // hop 1
    k_scale2<<<grid_nodes, TB>>>();
    k_edge_sorted<<<grid_edge, 1024, SMEM_TOTAL>>>(bp, cp);
    // hop 2
    k_div2<<<grid_nodes, TB>>>(cp, ap, bp);
    k_edge_sorted<<<grid_edge, 1024, SMEM_TOTAL>>>(ap, bp);
    // hop 3 (accumulate into d_out)
    k_div2<<<grid_nodes, TB>>>(bp, cp, out);
    k_edge_sorted<<<grid_edge, 1024, SMEM_TOTAL>>>(cp, out);

    k_final<<<grid_nodes, TB>>>(out, b);
}

// round 12
// speedup vs baseline: 1.0644x; 1.0644x over previous
#include <cuda_runtime.h>
#include <cstdint>

#define N_NODES 50000
#define N_EDGES 800000
#define N_FEATS 64
#define NQUADS  (N_EDGES / 4)
#define NBLOCKS 256          // <= 2 blocks/SM on >=128 SMs -> all co-resident

// Scratch (allocation-free)
__device__ int   g_dcnt[N_NODES];
__device__ float g_rsq [N_NODES];
__device__ float g_rdeg[N_NODES];
__device__ float g_a[N_NODES];
__device__ float g_b[N_NODES];
__device__ float g_c[N_NODES];

// Grid barrier state. g_cnt returns to 0 after every barrier; g_gen is a
// monotonic generation counter (only compared relatively -> replay-safe).
__device__ unsigned g_cnt_bar;
__device__ volatile unsigned g_gen_bar;

__device__ __forceinline__ void grid_barrier() {
    __syncthreads();
    if (threadIdx.x == 0) {
        __threadfence();                       // publish this block's writes
        unsigned gen = g_gen_bar;
        if (atomicAdd(&g_cnt_bar, 1u) == gridDim.x - 1) {
            g_cnt_bar = 0;
            __threadfence();
            g_gen_bar = gen + 1;               // release
        } else {
            while (g_gen_bar == gen) { }       // spin (lane 0 only)
        }
        __threadfence();                       // acquire
    }
    __syncthreads();
}

// Edge pass: dst[col] += src[row]; 4 edges/iter, gathers batched (MLP=4).
__device__ __forceinline__ void edge_pass(const int4* __restrict__ r4,
                                          const int4* __restrict__ c4,
                                          const float* __restrict__ src,
                                          float* __restrict__ dst,
                                          int tid, int nth) {
    for (int t = tid; t < NQUADS; t += nth) {
        int4 r = r4[t];
        int4 c = c4[t];
        float v0 = __ldg(src + r.x);
        float v1 = __ldg(src + r.y);
        float v2 = __ldg(src + r.z);
        float v3 = __ldg(src + r.w);
        atomicAdd(dst + c.x, v0);
        atomicAdd(dst + c.y, v1);
        atomicAdd(dst + c.z, v2);
        atomicAdd(dst + c.w, v3);
    }
}

__global__ void __launch_bounds__(1024, 2)
mega(const float* __restrict__ x, const int* __restrict__ ei,
     const float* __restrict__ W, const float* __restrict__ bias,
     float* __restrict__ out) {
    const int tid = blockIdx.x * 1024 + threadIdx.x;
    const int nth = gridDim.x * 1024;
    const int4* r4 = reinterpret_cast<const int4*>(ei);            // sources
    const int4* c4 = reinterpret_cast<const int4*>(ei + N_EDGES);  // dests

    // ---- P0: projection y0 = x[n,:].W (warp per node) + zero histogram ----
    {
        int gw = tid >> 5, lane = tid & 31, nw = nth >> 5;
        float w0 = __ldg(W + lane);
        float w1 = __ldg(W + lane + 32);
        for (int n = gw; n < N_NODES; n += nw) {
            const float* xr = x + (size_t)n * N_FEATS;
            float s = xr[lane] * w0 + xr[lane + 32] * w1;
            #pragma unroll
            for (int o = 16; o; o >>= 1) s += __shfl_xor_sync(0xFFFFFFFFu, s, o);
            if (lane == 0) g_a[n] = s;
        }
        for (int i = tid; i < N_NODES; i += nth) g_dcnt[i] = 0;
    }
    grid_barrier();

    // ---- P1: degree histogram at destination ----
    for (int t = tid; t < NQUADS; t += nth) {
        int4 c = c4[t];
        atomicAdd(&g_dcnt[c.x], 1);
        atomicAdd(&g_dcnt[c.y], 1);
        atomicAdd(&g_dcnt[c.z], 1);
        atomicAdd(&g_dcnt[c.w], 1);
    }
    grid_barrier();

    // ---- P2: deg = cnt+1 (self-loop); rsq, rdeg; u0 -> (b=src, c=acc) ----
    for (int i = tid; i < N_NODES; i += nth) {
        float d  = (float)(g_dcnt[i] + 1);
        float rs = rsqrtf(d);
        g_rsq[i]  = rs;
        g_rdeg[i] = rs * rs;
        float v = rs * g_a[i];      // u0 = rsqrt(deg) * y0
        g_b[i] = v;                 // gather source
        g_c[i] = v;                 // accumulator init = self-loop term
    }
    grid_barrier();

    // ---- hop 1 ----
    edge_pass(r4, c4, g_b, g_c, tid, nth);
    grid_barrier();

    // ---- D2: u1 = s1/deg -> (a=src, b=acc) ----
    for (int i = tid; i < N_NODES; i += nth) {
        float v = g_c[i] * g_rdeg[i];
        g_a[i] = v;
        g_b[i] = v;
    }
    grid_barrier();

    // ---- hop 2 ----
    edge_pass(r4, c4, g_a, g_b, tid, nth);
    grid_barrier();

    // ---- D3: u2 = s2/deg -> (c=src, out=acc) ----
    for (int i = tid; i < N_NODES; i += nth) {
        float v = g_b[i] * g_rdeg[i];
        g_c[i] = v;
        out[i] = v;
    }
    grid_barrier();

    // ---- hop 3 (into out) ----
    edge_pass(r4, c4, g_c, out, tid, nth);
    grid_barrier();

    // ---- F: out = rsqrt(deg) * s3 + bias ----
    {
        float bb = __ldg(bias);
        for (int i = tid; i < N_NODES; i += nth)
            out[i] = g_rsq[i] * out[i] + bb;
    }
}

extern "C" void kernel_launch(void* const* d_in, const int* in_sizes, int n_in,
                              void* d_out, int out_size) {
    const float* x  = (const float*)d_in[0];
    const int*   ei = (const int*)d_in[1];   // [2, N_EDGES]
    const float* W  = (const float*)d_in[2]; // [1, N_FEATS]
    const float* b  = (const float*)d_in[3]; // [1]
    float* out = (float*)d_out;              // [N_NODES, 1]

    mega<<<NBLOCKS, 1024>>>(x, ei, W, b, out);
}

// round 15
// speedup vs baseline: 1.4252x; 1.3389x over previous
#include <cuda_runtime.h>
#include <cstdint>

#define N_NODES 50000
#define N_EDGES 800000
#define N_FEATS 64
#define NHALF   (N_EDGES / 2)
#define NQUADS  (N_EDGES / 4)

// Scratch (allocation-free). g_dcnt is zero at module load and re-zeroed by
// k_final at the end of every invocation -> every call sees identical state.
__device__ int   g_dcnt[N_NODES];
__device__ float g_rsq [N_NODES];
__device__ float g_rdeg[N_NODES];
__device__ float g_a[N_NODES];
__device__ float g_b[N_NODES];
__device__ float g_c[N_NODES];

// ---------------------------------------------------------------------------
// Fused: degree histogram (4 edges/thread, int REDs) + projection
// y0 = x[n,:].W (warp per node). The two loops are independent; running both
// in one kernel hides the projection entirely under the histogram's
// wavefront floor and removes a launch gap.
// ---------------------------------------------------------------------------
__global__ void __launch_bounds__(256, 8)
k_fused_deg_proj(const float* __restrict__ x,
                 const int* __restrict__ col,
                 const float* __restrict__ W) {
    const int tid = blockIdx.x * blockDim.x + threadIdx.x;
    const int nth = gridDim.x * blockDim.x;

    // degree histogram at destination
    for (int t = tid; t < NQUADS; t += nth) {
        int4 c = reinterpret_cast<const int4*>(col)[t];
        atomicAdd(&g_dcnt[c.x], 1);
        atomicAdd(&g_dcnt[c.y], 1);
        atomicAdd(&g_dcnt[c.z], 1);
        atomicAdd(&g_dcnt[c.w], 1);
    }

    // projection (warp per node)
    const int gw = tid >> 5, lane = tid & 31, nw = nth >> 5;
    const float w0 = __ldg(W + lane);
    const float w1 = __ldg(W + lane + 32);
    for (int n = gw; n < N_NODES; n += nw) {
        const float* xr = x + (size_t)n * N_FEATS;
        float s = xr[lane] * w0 + xr[lane + 32] * w1;
        #pragma unroll
        for (int o = 16; o; o >>= 1) s += __shfl_xor_sync(0xFFFFFFFFu, s, o);
        if (lane == 0) g_a[n] = s;
    }
}

// ---------------------------------------------------------------------------
// deg = dcnt + 1 (self-loop); cache rsq/rdeg; u0 = rsq*y0 -> (src, acc).
// The accumulator copy IS the self-loop term of hop 1.
// ---------------------------------------------------------------------------
__global__ void k_scale2() {
    int i = blockIdx.x * blockDim.x + threadIdx.x;
    if (i >= N_NODES) return;
    float d  = (float)(g_dcnt[i] + 1);
    float rs = rsqrtf(d);
    g_rsq[i]  = rs;
    g_rdeg[i] = rs * rs;
    float v = rs * g_a[i];
    g_b[i] = v;   // gather source
    g_c[i] = v;   // accumulator init (self-loop)
}

// ---------------------------------------------------------------------------
// Edge pass (R2-proven config): dst[col] += src[row], 2 edges/thread,
// full-residency grid-stride.
// ---------------------------------------------------------------------------
__global__ void __launch_bounds__(256, 8)
k_edge(const int* __restrict__ row, const int* __restrict__ col,
       const float* __restrict__ src, float* __restrict__ dst) {
    int stride = gridDim.x * blockDim.x;
    for (int t = blockIdx.x * blockDim.x + threadIdx.x; t < NHALF; t += stride) {
        int2 r = reinterpret_cast<const int2*>(row)[t];
        int2 c = reinterpret_cast<const int2*>(col)[t];
        float vx = __ldg(src + r.x);
        float vy = __ldg(src + r.y);
        atomicAdd(dst + c.x, vx);
        atomicAdd(dst + c.y, vy);
    }
}

// ---------------------------------------------------------------------------
// Mid-hop: u' = s * rdeg -> next gather-source + accumulator.
// ---------------------------------------------------------------------------
__global__ void k_div2(const float* __restrict__ s,
                       float* __restrict__ u, float* __restrict__ s2) {
    int i = blockIdx.x * blockDim.x + threadIdx.x;
    if (i >= N_NODES) return;
    float v = s[i] * g_rdeg[i];
    u[i]  = v;
    s2[i] = v;
}

// ---------------------------------------------------------------------------
// Final: out = rsq * s3 + bias, and restore g_dcnt to zero so the next
// invocation sees identical initial state (deterministic, stateless-in-effect).
// ---------------------------------------------------------------------------
__global__ void k_final(float* __restrict__ out, const float* __restrict__ b) {
    int i = blockIdx.x * blockDim.x + threadIdx.x;
    if (i >= N_NODES) return;
    out[i] = g_rsq[i] * out[i] + __ldg(b);
    g_dcnt[i] = 0;
}

extern "C" void kernel_launch(void* const* d_in, const int* in_sizes, int n_in,
                              void* d_out, int out_size) {
    const float* x  = (const float*)d_in[0];
    const int*   ei = (const int*)d_in[1];   // [2, N_EDGES]
    const float* W  = (const float*)d_in[2]; // [1, N_FEATS]
    const float* b  = (const float*)d_in[3]; // [1]
    float* out = (float*)d_out;              // [N_NODES, 1]

    const int* row = ei;            // gather source
    const int* col = ei + N_EDGES;  // scatter destination

    float* ap; cudaGetSymbolAddress((void**)&ap, g_a);
    float* bp; cudaGetSymbolAddress((void**)&bp, g_b);
    float* cp; cudaGetSymbolAddress((void**)&cp, g_c);

    const int TB = 256;
    int grid_nodes = (N_NODES + TB - 1) / TB;
    int grid_edge  = 148 * 8;   // full residency at 256 thr/block

    // fused: degree histogram + projection (independent, overlapped)
    k_fused_deg_proj<<<grid_edge, TB>>>(x, col, W);

    // hop 1
    k_scale2<<<grid_nodes, TB>>>();
    k_edge<<<grid_edge, TB>>>(row, col, bp, cp);
    // hop 2
    k_div2<<<grid_nodes, TB>>>(cp, ap, bp);
    k_edge<<<grid_edge, TB>>>(row, col, ap, bp);
    // hop 3 (accumulate into d_out)
    k_div2<<<grid_nodes, TB>>>(bp, cp, out);
    k_edge<<<grid_edge, TB>>>(row, col, cp, out);

    // out = rsq*s3 + b ; restore histogram to zero for next invocation
    k_final<<<grid_nodes, TB>>>(out, b);
}

// round 16
// speedup vs baseline: 1.5551x; 1.0912x over previous
#include <cuda_runtime.h>
#include <cstdint>

#define N_NODES 50000
#define N_EDGES 800000
#define N_FEATS 64
#define NQUADS  (N_EDGES / 4)
#define NNQ     ((N_NODES + 3) / 4)     // node quads (12500)

// Scratch (allocation-free). g_dcnt is zero at module load and re-zeroed
// each invocation after use -> every call sees identical state.
__device__ int   g_dcnt[N_NODES];
__device__ float g_rsq [N_NODES];
__device__ float g_rdeg[N_NODES];
__device__ float g_a[N_NODES + 2];      // +pad so float4 tails are safe
__device__ float g_b[N_NODES + 2];
__device__ float g_c[N_NODES + 2];

// ---------------------------------------------------------------------------
// Fused: degree histogram (4 edges/thread) + projection (warp per node).
// First kernel in chain — no PDL sync needed.
// ---------------------------------------------------------------------------
__global__ void __launch_bounds__(256, 8)
k_fused_deg_proj(const float* __restrict__ x,
                 const int* __restrict__ col,
                 const float* __restrict__ W) {
    const int tid = blockIdx.x * blockDim.x + threadIdx.x;
    const int nth = gridDim.x * blockDim.x;

    for (int t = tid; t < NQUADS; t += nth) {
        int4 c = reinterpret_cast<const int4*>(col)[t];
        atomicAdd(&g_dcnt[c.x], 1);
        atomicAdd(&g_dcnt[c.y], 1);
        atomicAdd(&g_dcnt[c.z], 1);
        atomicAdd(&g_dcnt[c.w], 1);
    }

    const int gw = tid >> 5, lane = tid & 31, nw = nth >> 5;
    const float w0 = __ldg(W + lane);
    const float w1 = __ldg(W + lane + 32);
    for (int n = gw; n < N_NODES; n += nw) {
        const float* xr = x + (size_t)n * N_FEATS;
        float s = xr[lane] * w0 + xr[lane + 32] * w1;
        #pragma unroll
        for (int o = 16; o; o >>= 1) s += __shfl_xor_sync(0xFFFFFFFFu, s, o);
        if (lane == 0) g_a[n] = s;
    }
}

// ---------------------------------------------------------------------------
// scale2: deg = dcnt+1; rsq/rdeg; u0 = rsq*y0 -> (g_b src, g_c acc).
// Depends on everything from k_fused -> sync first, then work.
// ---------------------------------------------------------------------------
__global__ void k_scale2() {
    int i = blockIdx.x * blockDim.x + threadIdx.x;
    cudaGridDependencySynchronize();
    if (i >= N_NODES) return;
    float d  = (float)(g_dcnt[i] + 1);
    float rs = rsqrtf(d);
    g_rsq[i]  = rs;
    g_rdeg[i] = rs * rs;
    float v = rs * g_a[i];
    g_b[i] = v;   // gather source
    g_c[i] = v;   // accumulator init (self-loop term)
    g_dcnt[i] = 0;  // restore for next invocation (dcnt consumed above)
}

// ---------------------------------------------------------------------------
// Edge pass: dst[col] += src[row]. ONE quad per thread so ALL index loads
// (inputs; independent of predecessor) issue BEFORE the PDL sync, fully
// overlapped with the predecessor's tail. Gathers+REDs after sync.
// ---------------------------------------------------------------------------
__global__ void __launch_bounds__(256)
k_edge(const int* __restrict__ row, const int* __restrict__ col,
       const float* __restrict__ src, float* __restrict__ dst) {
    int t = blockIdx.x * blockDim.x + threadIdx.x;
    int4 r, c;
    bool act = t < NQUADS;
    if (act) {
        r = reinterpret_cast<const int4*>(row)[t];   // pre-sync (input data)
        c = reinterpret_cast<const int4*>(col)[t];
    }
    cudaGridDependencySynchronize();
    if (!act) return;
    float v0 = __ldg(src + r.x);
    float v1 = __ldg(src + r.y);
    float v2 = __ldg(src + r.z);
    float v3 = __ldg(src + r.w);
    atomicAdd(dst + c.x, v0);
    atomicAdd(dst + c.y, v1);
    atomicAdd(dst + c.z, v2);
    atomicAdd(dst + c.w, v3);
}

// ---------------------------------------------------------------------------
// Mid-hop: u' = s * rdeg -> next gather-source + accumulator.
// 4 nodes/thread; rdeg (stable since scale2) preloaded pre-sync.
// Writes (incl. WAR on the previous edge pass's src array) strictly post-sync.
// ---------------------------------------------------------------------------
__global__ void __launch_bounds__(256)
k_div2(const float* __restrict__ s, float* __restrict__ u,
       float* __restrict__ s2) {
    int q = blockIdx.x * blockDim.x + threadIdx.x;
    bool act = q < NNQ;
    float4 rd;
    if (act) rd = *reinterpret_cast<const float4*>(g_rdeg + q * 4);  // pre-sync
    cudaGridDependencySynchronize();
    if (!act) return;
    float4 sv = *reinterpret_cast<const float4*>(s + q * 4);
    float4 v;
    v.x = sv.x * rd.x; v.y = sv.y * rd.y;
    v.z = sv.z * rd.z; v.w = sv.w * rd.w;
    *reinterpret_cast<float4*>(u  + q * 4) = v;
    *reinterpret_cast<float4*>(s2 + q * 4) = v;
}

// ---------------------------------------------------------------------------
// Final: out = rsq * s3 + bias. rsq + bias preloaded pre-sync.
// out is both input (s3, written by edge pass 3) and output -> scalar loop
// guarded to N_NODES exactly (out buffer is exactly N_NODES floats).
// ---------------------------------------------------------------------------
__global__ void __launch_bounds__(256)
k_final(float* __restrict__ out, const float* __restrict__ b) {
    int i = blockIdx.x * blockDim.x + threadIdx.x;
    float rs = (i < N_NODES) ? g_rsq[i] : 0.f;   // pre-sync (stable)
    float bb = __ldg(b);                         // pre-sync (input)
    cudaGridDependencySynchronize();
    if (i >= N_NODES) return;
    out[i] = rs * out[i] + bb;
}

// ---------------------------------------------------------------------------
// PDL launcher: consumer may launch while producer drains; it self-orders
// via cudaGridDependencySynchronize().
// ---------------------------------------------------------------------------
template <typename... Args>
static inline void launch_pdl(void (*ker)(Args...), int grid, int block,
                              Args... args) {
    cudaLaunchConfig_t cfg = {};
    cfg.gridDim  = dim3(grid, 1, 1);
    cfg.blockDim = dim3(block, 1, 1);
    cfg.stream   = 0;
    cudaLaunchAttribute at[1];
    at[0].id = cudaLaunchAttributeProgrammaticStreamSerialization;
    at[0].val.programmaticStreamSerializationAllowed = 1;
    cfg.attrs = at;
    cfg.numAttrs = 1;
    cudaLaunchKernelEx(&cfg, ker, args...);
}

extern "C" void kernel_launch(void* const* d_in, const int* in_sizes, int n_in,
                              void* d_out, int out_size) {
    const float* x  = (const float*)d_in[0];
    const int*   ei = (const int*)d_in[1];   // [2, N_EDGES]
    const float* W  = (const float*)d_in[2]; // [1, N_FEATS]
    const float* b  = (const float*)d_in[3]; // [1]
    float* out = (float*)d_out;              // [N_NODES, 1]

    const int* row = ei;            // gather source
    const int* col = ei + N_EDGES;  // scatter destination

    float* ap; cudaGetSymbolAddress((void**)&ap, g_a);
    float* bp; cudaGetSymbolAddress((void**)&bp, g_b);
    float* cp; cudaGetSymbolAddress((void**)&cp, g_c);

    const int TB = 256;
    int grid_nodes = (N_NODES + TB - 1) / TB;          // 196
    int grid_nq    = (NNQ + TB - 1) / TB;              // 49
    int grid_quads = (NQUADS + TB - 1) / TB;           // 782
    int grid_hist  = 148 * 8;

    // fused: histogram + projection (plain launch, head of chain)
    k_fused_deg_proj<<<grid_hist, TB>>>(x, col, W);

    // hop 1
    launch_pdl(k_scale2, grid_nodes, TB);
    launch_pdl(k_edge, grid_quads, TB, row, col, (const float*)bp, cp);
    // hop 2
    launch_pdl(k_div2, grid_nq, TB, (const float*)cp, ap, bp);
    launch_pdl(k_edge, grid_quads, TB, row, col, (const float*)ap, bp);
    // hop 3 (accumulate into d_out)
    launch_pdl(k_div2, grid_nq, TB, (const float*)bp, cp, out);
    launch_pdl(k_edge, grid_quads, TB, row, col, (const float*)cp, out);
    // out = rsq*s3 + b
    launch_pdl(k_final, grid_nodes, TB, out, b);
}